// round 1
// baseline (speedup 1.0000x reference)
#include <cuda_runtime.h>
#include <cuda_bf16.h>

// C = triu(A @ B), A and B upper-triangular, N=4096, fp32.
// Round 1: SIMT fp32 baseline with triangular tile skipping.
//  - Only upper-triangular 128x128 output tiles are computed (528 of 1024).
//  - Per tile (it,jt), K loop restricted to [it*128, (jt+1)*128).
//  - Blocks scheduled longest-K-first (descending diagonal) to cut tail latency.
//  - Lower triangle zeroed via cudaMemsetAsync (graph-capturable memset node).

#define BM 128
#define BN 128
#define BK 16
#define TM 8
#define TN 8
#define NTHREADS 256  // (BM/TM)*(BN/TN)

__global__ __launch_bounds__(NTHREADS, 2)
void triu_gemm_f32_kernel(const float* __restrict__ A,
                          const float* __restrict__ B,
                          float* __restrict__ C,
                          int N)
{
    const int nt = N / BM;  // 32 tiles per dim

    // Map blockIdx.x -> (it, jt) over upper-triangular tiles, heaviest
    // diagonals (largest jt-it) first so long-running CTAs start early.
    int rem = blockIdx.x;
    int d = nt - 1;
    while (rem >= nt - d) { rem -= nt - d; d--; }
    const int it = rem;
    const int jt = it + d;

    __shared__ float As[BK][BM];   // A tile, transposed: As[k][m]
    __shared__ float Bs[BK][BN];   // B tile: Bs[k][n]

    const int tid = threadIdx.x;
    const int tx = tid & 15;       // 0..15 -> output column group
    const int ty = tid >> 4;       // 0..15 -> output row group

    const int row0 = it * BM;
    const int col0 = jt * BN;

    float acc[TM][TN];
#pragma unroll
    for (int i = 0; i < TM; i++)
#pragma unroll
        for (int j = 0; j < TN; j++)
            acc[i][j] = 0.0f;

    // K range where both A (k >= i) and B (k <= j) are nonzero.
    const int k_beg = it * BM;
    const int k_end = (jt + 1) * BN;

    for (int k0 = k_beg; k0 < k_end; k0 += BK) {
        // ---- Load A tile (BM x BK) as float4 along k, store transposed ----
        // 128 rows * 4 float4-groups = 512 float4 loads; 2 per thread.
#pragma unroll
        for (int s = 0; s < 2; s++) {
            const int l  = tid + s * NTHREADS;   // 0..511
            const int r  = l >> 2;               // row within tile 0..127
            const int kq = (l & 3) * 4;          // k sub-offset 0,4,8,12
            float4 v = *reinterpret_cast<const float4*>(
                &A[(size_t)(row0 + r) * N + k0 + kq]);
            As[kq + 0][r] = v.x;
            As[kq + 1][r] = v.y;
            As[kq + 2][r] = v.z;
            As[kq + 3][r] = v.w;
        }
        // ---- Load B tile (BK x BN) as float4 along n ----
#pragma unroll
        for (int s = 0; s < 2; s++) {
            const int l  = tid + s * NTHREADS;   // 0..511
            const int r  = l >> 5;               // k row within tile 0..15
            const int cq = (l & 31) * 4;         // col offset 0..124
            float4 v = *reinterpret_cast<const float4*>(
                &B[(size_t)(k0 + r) * N + col0 + cq]);
            *reinterpret_cast<float4*>(&Bs[r][cq]) = v;
        }
        __syncthreads();

        // ---- Compute 8x8 outer products over BK k-steps ----
#pragma unroll
        for (int kk = 0; kk < BK; kk++) {
            float af[TM], bf[TN];
#pragma unroll
            for (int i = 0; i < TM; i++) af[i] = As[kk][ty * TM + i];
#pragma unroll
            for (int j = 0; j < TN; j++) bf[j] = Bs[kk][tx * TN + j];
#pragma unroll
            for (int i = 0; i < TM; i++)
#pragma unroll
                for (int j = 0; j < TN; j++)
                    acc[i][j] = fmaf(af[i], bf[j], acc[i][j]);
        }
        __syncthreads();
    }

    // ---- Store with triu mask (only matters on diagonal tiles) ----
#pragma unroll
    for (int i = 0; i < TM; i++) {
        const int grow = row0 + ty * TM + i;
#pragma unroll
        for (int j = 0; j < TN; j += 4) {
            const int gcol = col0 + tx * TN + j;
            float4 v;
            v.x = (gcol + 0 >= grow) ? acc[i][j + 0] : 0.0f;
            v.y = (gcol + 1 >= grow) ? acc[i][j + 1] : 0.0f;
            v.z = (gcol + 2 >= grow) ? acc[i][j + 2] : 0.0f;
            v.w = (gcol + 3 >= grow) ? acc[i][j + 3] : 0.0f;
            *reinterpret_cast<float4*>(&C[(size_t)grow * N + gcol]) = v;
        }
    }
}

extern "C" void kernel_launch(void* const* d_in, const int* in_sizes, int n_in,
                              void* d_out, int out_size) {
    const float* A = (const float*)d_in[0];
    const float* B = (const float*)d_in[1];
    float* C = (float*)d_out;
    const int N = 4096;

    // Zero the whole output (covers the untouched strictly-lower tiles).
    cudaMemsetAsync(d_out, 0, (size_t)N * N * sizeof(float), 0);

    const int nt = N / BM;                  // 32
    const int nblocks = nt * (nt + 1) / 2;  // 528 upper-triangular tiles
    triu_gemm_f32_kernel<<<nblocks, NTHREADS>>>(A, B, C, N);
}

// round 3
// speedup vs baseline: 3.6172x; 3.6172x over previous
#include <cuda_runtime.h>
#include <cstdint>

// C = triu(A @ B), A,B upper-triangular fp32, N=4096.
// Round 3: Ampere-compatible TF32 mma.sync tensor-core GEMM (the harness's
// virtual arch is compute_103, so tcgen05/sm_103a-only PTX is unavailable).
//   - 128x128 output tiles over upper triangle (528 CTAs), longest-K first.
//   - K restricted to [it*128, (jt+1)*128).
//   - 4-stage cp.async pipeline, padded smem (conflict-free LDS).
//   - In-register cvt.rna.tf32 rounding (unbiased) before mma.
//   - Lower triangle zeroed via cudaMemsetAsync.

#define N_DIM 4096
#define BM 128
#define BN 128
#define BK 32
#define STAGES 4
#define NTHREADS 256

#define AP 36    // A smem row pitch (floats): bank = (4*row + col) % 32 -> conflict-free
#define BP 136   // B smem row pitch (floats): bank = (8*k + n) % 32   -> conflict-free
#define A_STAGE_FL (BM * AP)              // 4608 floats
#define B_STAGE_FL (BK * BP)              // 4352 floats
#define B_BASE_FL  (STAGES * A_STAGE_FL)  // 18432
#define SMEM_FL    (B_BASE_FL + STAGES * B_STAGE_FL)  // 35840 floats = 143360 B

__device__ __forceinline__ uint32_t smem_u32(const void* p) {
    uint32_t a;
    asm("{ .reg .u64 t; cvta.to.shared.u64 t, %1; cvt.u32.u64 %0, t; }" : "=r"(a) : "l"(p));
    return a;
}
__device__ __forceinline__ void cp_async16(uint32_t dst, const float* src) {
    asm volatile("cp.async.cg.shared.global [%0], [%1], 16;" :: "r"(dst), "l"(src));
}
__device__ __forceinline__ uint32_t ld_tf32(const float* p) {
    uint32_t r;
    float v = *p;
    asm("cvt.rna.tf32.f32 %0, %1;" : "=r"(r) : "f"(v));
    return r;
}

__global__ __launch_bounds__(NTHREADS, 1)
void triu_gemm_tf32mma_kernel(const float* __restrict__ A,
                              const float* __restrict__ B,
                              float* __restrict__ C)
{
    extern __shared__ float sm[];
    const uint32_t smb = smem_u32(sm);

    const int tid  = threadIdx.x;
    const int wid  = tid >> 5;
    const int lane = tid & 31;
    const int qrow = lane >> 2;   // 0..7
    const int qcol = lane & 3;    // 0..3

    // Decode blockIdx -> (it, jt), longest-K diagonals first.
    int rem = blockIdx.x;
    int d = 31;
    while (rem >= 32 - d) { rem -= 32 - d; d--; }
    const int it = rem;
    const int jt = it + d;

    const int row0  = it * BM;
    const int col0  = jt * BN;
    const int k_beg = it * BM;
    const int nch   = (jt - it + 1) * (BM / BK);   // >= 4 chunks of BK=32

    // Warp tile: 64(m) x 32(n); warps arranged 2(m) x 4(n).
    const int wm = (wid & 1) * 64;
    const int wn = (wid >> 1) * 32;

    float acc[4][4][4];   // [mt][nt][creg]
#pragma unroll
    for (int i = 0; i < 4; i++)
#pragma unroll
        for (int j = 0; j < 4; j++)
#pragma unroll
            for (int r = 0; r < 4; r++) acc[i][j][r] = 0.0f;

    // ---- cp.async staging helpers (addresses precomputed per thread) ----
    // A tile: 128 rows x 32 floats; thread covers 4 x 16B segs.
    const int arow = tid >> 3;          // base row 0..31 (+32 per rep)
    const int aseg = tid & 7;           // 16B seg within row
    // B tile: 32 rows x 128 floats; thread covers 4 x 16B segs.
    const int brow = tid >> 5;          // base row 0..7 (+8 per rep)
    const int bseg = tid & 31;

    const float* Ag = A + (size_t)(row0 + arow) * N_DIM + aseg * 4;
    const float* Bg = B + (size_t)brow * N_DIM + col0 + bseg * 4;

#define LOAD_STAGE(s, kc)                                                        \
    do {                                                                         \
        const uint32_t abase = smb + ((s) * A_STAGE_FL) * 4;                     \
        const uint32_t bbase = smb + (B_BASE_FL + (s) * B_STAGE_FL) * 4;         \
        _Pragma("unroll")                                                        \
        for (int r = 0; r < 4; r++)                                             \
            cp_async16(abase + ((arow + r * 32) * AP + aseg * 4) * 4,            \
                       Ag + (size_t)(r * 32) * N_DIM + (kc));                    \
        _Pragma("unroll")                                                        \
        for (int r = 0; r < 4; r++)                                             \
            cp_async16(bbase + ((brow + r * 8) * BP + bseg * 4) * 4,             \
                       Bg + (size_t)((kc) + r * 8) * N_DIM);                     \
    } while (0)

    // Prologue: stages 0..2
#pragma unroll
    for (int s = 0; s < STAGES - 1; s++) {
        LOAD_STAGE(s, k_beg + s * BK);
        asm volatile("cp.async.commit_group;" ::: "memory");
    }

    for (int i = 0; i < nch; i++) {
        asm volatile("cp.async.wait_group %0;" :: "n"(STAGES - 2) : "memory");
        __syncthreads();

        // Issue next stage (or empty group to keep wait_group accounting exact).
        if (i + STAGES - 1 < nch)
            LOAD_STAGE((i + STAGES - 1) & (STAGES - 1), k_beg + (i + STAGES - 1) * BK);
        asm volatile("cp.async.commit_group;" ::: "memory");

        // ---- Compute stage i ----
        const int s = i & (STAGES - 1);
        const float* As = sm + s * A_STAGE_FL;
        const float* Bs = sm + B_BASE_FL + s * B_STAGE_FL;

#pragma unroll
        for (int ks = 0; ks < BK / 8; ks++) {
            const int k0 = ks * 8;
            uint32_t af[4][4], bf[4][2];
#pragma unroll
            for (int mt = 0; mt < 4; mt++) {
                const float* ap = As + (wm + mt * 16 + qrow) * AP + k0 + qcol;
                af[mt][0] = ld_tf32(ap);
                af[mt][1] = ld_tf32(ap + 8 * AP);
                af[mt][2] = ld_tf32(ap + 4);
                af[mt][3] = ld_tf32(ap + 8 * AP + 4);
            }
#pragma unroll
            for (int nt = 0; nt < 4; nt++) {
                const float* bp = Bs + (k0 + qcol) * BP + wn + nt * 8 + qrow;
                bf[nt][0] = ld_tf32(bp);
                bf[nt][1] = ld_tf32(bp + 4 * BP);
            }
#pragma unroll
            for (int mt = 0; mt < 4; mt++)
#pragma unroll
                for (int nt = 0; nt < 4; nt++) {
                    asm volatile(
                        "mma.sync.aligned.m16n8k8.row.col.f32.tf32.tf32.f32 "
                        "{%0,%1,%2,%3}, {%4,%5,%6,%7}, {%8,%9}, {%0,%1,%2,%3};"
                        : "+f"(acc[mt][nt][0]), "+f"(acc[mt][nt][1]),
                          "+f"(acc[mt][nt][2]), "+f"(acc[mt][nt][3])
                        : "r"(af[mt][0]), "r"(af[mt][1]),
                          "r"(af[mt][2]), "r"(af[mt][3]),
                          "r"(bf[nt][0]), "r"(bf[nt][1]));
                }
        }
        __syncthreads();
    }

    // ---- Epilogue: masked stores (triu), float2 per c-reg pair ----
#pragma unroll
    for (int mt = 0; mt < 4; mt++) {
        const int r_lo = row0 + wm + mt * 16 + qrow;
        const int r_hi = r_lo + 8;
        float* crow_lo = C + (size_t)r_lo * N_DIM;
        float* crow_hi = C + (size_t)r_hi * N_DIM;
#pragma unroll
        for (int nt = 0; nt < 4; nt++) {
            const int gc = col0 + wn + nt * 8 + qcol * 2;
            float2 v0, v1;
            v0.x = (gc + 0 >= r_lo) ? acc[mt][nt][0] : 0.0f;
            v0.y = (gc + 1 >= r_lo) ? acc[mt][nt][1] : 0.0f;
            v1.x = (gc + 0 >= r_hi) ? acc[mt][nt][2] : 0.0f;
            v1.y = (gc + 1 >= r_hi) ? acc[mt][nt][3] : 0.0f;
            *reinterpret_cast<float2*>(crow_lo + gc) = v0;
            *reinterpret_cast<float2*>(crow_hi + gc) = v1;
        }
    }
}

extern "C" void kernel_launch(void* const* d_in, const int* in_sizes, int n_in,
                              void* d_out, int out_size) {
    const float* A = (const float*)d_in[0];
    const float* B = (const float*)d_in[1];
    float* C = (float*)d_out;

    cudaFuncSetAttribute(triu_gemm_tf32mma_kernel,
                         cudaFuncAttributeMaxDynamicSharedMemorySize,
                         SMEM_FL * sizeof(float));

    // Zero lower triangle (untouched tiles).
    cudaMemsetAsync(d_out, 0, (size_t)N_DIM * N_DIM * sizeof(float), 0);

    // 528 upper-triangular 128x128 tiles, longest-K diagonals first.
    triu_gemm_tf32mma_kernel<<<528, NTHREADS, SMEM_FL * sizeof(float)>>>(A, B, C);
}